// round 14
// baseline (speedup 1.0000x reference)
#include <cuda_runtime.h>
#include <cuda_fp16.h>
#include <math.h>
#include <stdint.h>

// ---------------- problem constants ----------------
#define B_   256
#define T_   100
#define IN_  6
#define D_   1024
#define H_   8
#define L_   4
#define OUT_ 256
#define HD_  128
#define M_   (B_ * T_)         // 25600
#define KTOT_ (T_ * D_)        // 102400
#define SPLITF_ 100            // kchunk = 1024
#define SCALE_ 0.08838834764831845f

// ---------------- GEMM tiling ----------------
// 512 threads (16 warps, 4x4), warp tile 32x64, BN=256 (halves A-staging LSU
// cost per FLOP). A via cp.async+ldmatrix 4-stage; B via LDG.128 from
// fragment-pair-permuted weights (no B smem, no B double-buffer).
#define BM 128
#define BN 256
#define BK 64
#define LDSH 72                             // A row pitch 144B, conflict-free
#define STAGE_H (BM * LDSH)                 // 9216 halves = 18432 B
#define STAGES 4
#define GEMM_SMEM (STAGES * STAGE_H * 2)    // 73728 B

// ---------------- scratch (device globals) ----------------
__device__ float  g_h[M_ * D_];
__device__ float  g_tmp[M_ * D_];
__device__ float  g_part[SPLITF_ * B_ * OUT_];
__device__ __half g_h16[M_ * D_];
__device__ __half g_qkv16[M_ * 3 * D_];
__device__ __half g_ctx16[M_ * D_];
__device__ __half g_ff16[M_ * D_];
// fragment-pair-permuted weights: uint4 per (pair, lane); pair idx = kf*NP + np
__device__ uint4  g_qkvwp[L_ * 3 * D_ * D_ / 8];
__device__ uint4  g_outwp[L_ * D_ * D_ / 8];
__device__ uint4  g_ff1wp[L_ * D_ * D_ / 8];
__device__ uint4  g_ff2wp[L_ * D_ * D_ / 8];
__device__ uint4  g_wotp[(size_t)OUT_ * KTOT_ / 8];

// ---------------- helpers ----------------
__device__ __forceinline__ uint32_t smem_u32(const void* p) {
    uint32_t a;
    asm("{ .reg .u64 t; cvta.to.shared.u64 t, %1; cvt.u32.u64 %0, t; }" : "=r"(a) : "l"(p));
    return a;
}
#define CP_ASYNC16(dst, src) asm volatile("cp.async.cg.shared.global [%0], [%1], 16;" :: "r"(dst), "l"(src) : "memory")
#define CP_COMMIT()          asm volatile("cp.async.commit_group;" ::: "memory")
#define CP_WAIT2()           asm volatile("cp.async.wait_group 2;" ::: "memory")

__device__ __forceinline__ void ldsm_x4(uint32_t* r, uint32_t addr) {
    asm volatile("ldmatrix.sync.aligned.m8n8.x4.shared.b16 {%0,%1,%2,%3}, [%4];"
                 : "=r"(r[0]), "=r"(r[1]), "=r"(r[2]), "=r"(r[3]) : "r"(addr));
}

__device__ __forceinline__ void mma_f16(float* d, const uint32_t* a, uint32_t b0, uint32_t b1) {
    asm volatile(
        "mma.sync.aligned.m16n8k16.row.col.f32.f16.f16.f32 "
        "{%0,%1,%2,%3}, {%4,%5,%6,%7}, {%8,%9}, {%0,%1,%2,%3};"
        : "+f"(d[0]), "+f"(d[1]), "+f"(d[2]), "+f"(d[3])
        : "r"(a[0]), "r"(a[1]), "r"(a[2]), "r"(a[3]), "r"(b0), "r"(b1));
}

__device__ __forceinline__ float4 h4tof4(uint32_t u0, uint32_t u1) {
    float2 f0 = __half22float2(*(__half2*)&u0);
    float2 f1 = __half22float2(*(__half2*)&u1);
    return make_float4(f0.x, f0.y, f1.x, f1.y);
}

// ===== fp16 GEMM: BN=256, A smem+ldmatrix (4-stage), B LDG.128 permuted ====
// C[M,N] = A[M,lda] @ W^T (+bias)(+res)(+relu). grid (N/BN, M/BM, splits).
template <bool RELU, bool HASBIAS, bool HOUT, bool ADDRES>
__global__ void __launch_bounds__(512, 1)
tc_gemm(const __half* __restrict__ A, const uint4* __restrict__ Wp,
        const float* __restrict__ bias, const float* __restrict__ res,
        void* __restrict__ Cv, int M, int N, int lda, int kchunk,
        int NP, int ncoff) {
    extern __shared__ __half smh[];
    uint32_t sbase = smem_u32(smh);

    int tid = threadIdx.x;
    int lane = tid & 31, wid = tid >> 5;
    int wm = wid & 3, wn = wid >> 2;                 // 4x4 grid, 32x64 per warp
    int m0 = blockIdx.y * BM, n0 = blockIdx.x * BN;
    int kbeg = blockIdx.z * kchunk;
    int kf0 = kbeg >> 4;
    int npw = (ncoff + n0 + wn * 64) >> 4;           // first of 4 B frag-pairs

    // A cp.async: 128 rows x 8 x 16B chunks = 1024, 2 per thread
    const __half* asrc[2];
    uint32_t adst[2];
#pragma unroll
    for (int j = 0; j < 2; j++) {
        int c = tid + 512 * j;
        int r = c >> 3, c8 = c & 7;
        asrc[j] = A + (size_t)(m0 + r) * lda + kbeg + c8 * 8;
        adst[j] = (uint32_t)(r * LDSH + c8 * 8) * 2;
    }

    float acc[2][8][4];
#pragma unroll
    for (int tm = 0; tm < 2; tm++)
#pragma unroll
        for (int tn = 0; tn < 8; tn++)
#pragma unroll
            for (int c = 0; c < 4; c++) acc[tm][tn][c] = 0.f;

    const int NITER = kchunk / BK;

    // prologue: A stages 0, 1, 2
#pragma unroll
    for (int s = 0; s < 3; s++) {
        uint32_t sb = sbase + (uint32_t)(s * STAGE_H * 2);
        int ko = s * BK;
        CP_ASYNC16(sb + adst[0], asrc[0] + ko);
        CP_ASYNC16(sb + adst[1], asrc[1] + ko);
        CP_COMMIT();
    }

    int lrow = lane & 15;
    int lkb  = (lane >> 4) * 16;
    int buf = 0;

    for (int it = 0; it < NITER; it++) {
        CP_WAIT2();
        __syncthreads();

        // prefetch A stage it+3 before compute
        if (it + 3 < NITER) {
            int s = it + 3;
            uint32_t sbs = sbase + (uint32_t)((s & (STAGES - 1)) * STAGE_H * 2);
            int ko = s * BK;
            CP_ASYNC16(sbs + adst[0], asrc[0] + ko);
            CP_ASYNC16(sbs + adst[1], asrc[1] + ko);
        }
        CP_COMMIT();

        uint32_t sa = sbase + (uint32_t)(buf * STAGE_H * 2)
                    + (uint32_t)((wm * 32 + lrow) * (LDSH * 2)) + lkb;

#pragma unroll
        for (int ks = 0; ks < 4; ks++) {
            // B fragment pairs: 4 x LDG.128 per warp (coalesced)
            int kf = kf0 + it * 4 + ks;
            const uint4* bp = Wp + ((size_t)kf * NP + npw) * 32 + lane;
            uint4 bf[4];
#pragma unroll
            for (int f = 0; f < 4; f++) bf[f] = __ldg(bp + f * 32);

            int kbyte = ks * 32;
            uint32_t afr[2][4];
            ldsm_x4(afr[0], sa + kbyte);
            ldsm_x4(afr[1], sa + 16 * (LDSH * 2) + kbyte);
#pragma unroll
            for (int tnp = 0; tnp < 4; tnp++) {
                mma_f16(acc[0][tnp * 2],     afr[0], bf[tnp].x, bf[tnp].y);
                mma_f16(acc[0][tnp * 2 + 1], afr[0], bf[tnp].z, bf[tnp].w);
                mma_f16(acc[1][tnp * 2],     afr[1], bf[tnp].x, bf[tnp].y);
                mma_f16(acc[1][tnp * 2 + 1], afr[1], bf[tnp].z, bf[tnp].w);
            }
        }

        buf = (buf + 1) & (STAGES - 1);
    }

    // ---- epilogue: bias + residual + relu ----
    int q = lane & 3, g = lane >> 2;
#pragma unroll
    for (int tm = 0; tm < 2; tm++) {
        int row = m0 + wm * 32 + tm * 16 + g;
#pragma unroll
        for (int tn = 0; tn < 8; tn++) {
            int col = n0 + wn * 64 + tn * 8 + 2 * q;
            float b0 = 0.f, b1 = 0.f;
            if (HASBIAS) { b0 = bias[col]; b1 = bias[col + 1]; }
            float v00 = acc[tm][tn][0] + b0, v01 = acc[tm][tn][1] + b1;
            float v10 = acc[tm][tn][2] + b0, v11 = acc[tm][tn][3] + b1;
            if (ADDRES) {
                float2 r0 = *(const float2*)(res + (size_t)row * N + col);
                float2 r1 = *(const float2*)(res + (size_t)(row + 8) * N + col);
                v00 += r0.x; v01 += r0.y; v10 += r1.x; v11 += r1.y;
            }
            if (RELU) {
                v00 = fmaxf(v00, 0.f); v01 = fmaxf(v01, 0.f);
                v10 = fmaxf(v10, 0.f); v11 = fmaxf(v11, 0.f);
            }
            if (HOUT) {
                __half* C = (__half*)Cv + (size_t)blockIdx.z * M * N;
                *(__half2*)(C + (size_t)row * N + col) = __floats2half2_rn(v00, v01);
                *(__half2*)(C + (size_t)(row + 8) * N + col) = __floats2half2_rn(v10, v11);
            } else {
                float* C = (float*)Cv + (size_t)blockIdx.z * M * N;
                *(float2*)(C + (size_t)row * N + col) = make_float2(v00, v01);
                *(float2*)(C + (size_t)(row + 8) * N + col) = make_float2(v10, v11);
            }
        }
    }
}

// ---- weight prep: W[N,K] fp32 -> fragment-PAIR-permuted fp16 uint4 ----
__global__ void permw(const float* __restrict__ W, uint4* __restrict__ Wp,
                      int N, int K, size_t wstride, size_t pstride) {
    const float* Wl = W + wstride * blockIdx.y;
    uint4* Wpl = Wp + pstride * blockIdx.y;
    size_t idx = (size_t)blockIdx.x * 256 + threadIdx.x;
    int lane = (int)(idx & 31);
    size_t pr = idx >> 5;
    int NP = N >> 4;
    int np = (int)(pr % NP), kf = (int)(pr / NP);
    int ne = np * 16 + (lane >> 2);
    int k = kf * 16 + 2 * (lane & 3);
    const float* pe = Wl + (size_t)ne * K + k;
    const float* po = pe + (size_t)8 * K;
    __half2 xe = __floats2half2_rn(pe[0], pe[1]);
    __half2 ye = __floats2half2_rn(pe[8], pe[9]);
    __half2 xo = __floats2half2_rn(po[0], po[1]);
    __half2 yo = __floats2half2_rn(po[8], po[9]);
    Wpl[idx] = make_uint4(*(uint32_t*)&xe, *(uint32_t*)&ye,
                          *(uint32_t*)&xo, *(uint32_t*)&yo);
}

__global__ void permwo(const float* __restrict__ Wo, uint4* __restrict__ Wp) {
    size_t idx = (size_t)blockIdx.x * 256 + threadIdx.x;
    int lane = (int)(idx & 31);
    size_t pr = idx >> 5;
    const int NP = OUT_ >> 4;
    int np = (int)(pr % NP), kf = (int)(pr / NP);
    int ne = np * 16 + (lane >> 2);
    int k = kf * 16 + 2 * (lane & 3);
    const float* pe = Wo + (size_t)k * OUT_ + ne;
    __half2 xe = __floats2half2_rn(pe[0], pe[OUT_]);
    __half2 ye = __floats2half2_rn(pe[(size_t)8 * OUT_], pe[(size_t)9 * OUT_]);
    __half2 xo = __floats2half2_rn(pe[8], pe[OUT_ + 8]);
    __half2 yo = __floats2half2_rn(pe[(size_t)8 * OUT_ + 8], pe[(size_t)9 * OUT_ + 8]);
    Wp[idx] = make_uint4(*(uint32_t*)&xe, *(uint32_t*)&ye,
                         *(uint32_t*)&xo, *(uint32_t*)&yo);
}

// ---------------- embed ----------------
__global__ void embed_kernel(const float* __restrict__ x, const float* __restrict__ Wi,
                             const float* __restrict__ bi,
                             float* __restrict__ h, __half* __restrict__ h16) {
    int row = blockIdx.x;
    int t = row % T_;
    int d0 = threadIdx.x * 4;
    float xr[IN_];
#pragma unroll
    for (int j = 0; j < IN_; j++) xr[j] = x[row * IN_ + j];
    float4 o; float* op = &o.x;
#pragma unroll
    for (int c = 0; c < 4; c++) {
        int d = d0 + c;
        float acc = bi[d];
#pragma unroll
        for (int j = 0; j < IN_; j++) acc += xr[j] * Wi[j * D_ + d];
        int i2 = (d >> 1) * 2;
        float div = expf((float)i2 * (-9.210340371976184f / (float)D_));
        float ang = (float)t * div;
        acc += (d & 1) ? cosf(ang) : sinf(ang);
        op[c] = acc;
    }
    *(float4*)(h + (size_t)row * D_ + d0) = o;
    __half2* hp = (__half2*)(h16 + (size_t)row * D_ + d0);
    hp[0] = __floats2half2_rn(o.x, o.y);
    hp[1] = __floats2half2_rn(o.z, o.w);
}

// ---------------- fused attention per (b, h) ----------------
__global__ void attn_kernel(const __half* __restrict__ qkv, __half* __restrict__ ctx) {
    extern __shared__ float smf[];
    float* Ks = smf;
    float* Vs = smf + T_ * HD_;
    __shared__ float sbuf[8][104];

    int h = blockIdx.x, b = blockIdx.y;
    int tid = threadIdx.x, lane = tid & 31, w = tid >> 5;
    const __half* base = qkv + (size_t)b * T_ * 3 * D_;

    for (int idx = tid; idx < T_ * (HD_ / 8); idx += 256) {
        int k = idx >> 4, dq = idx & 15;
        const __half* rp = base + (size_t)k * 3 * D_ + h * HD_ + dq * 8;
        uint4 kv = *(const uint4*)(rp + D_);
        uint4 vv = *(const uint4*)(rp + 2 * D_);
        ((float4*)Ks)[idx * 2]     = h4tof4(kv.x, kv.y);
        ((float4*)Ks)[idx * 2 + 1] = h4tof4(kv.z, kv.w);
        ((float4*)Vs)[idx * 2]     = h4tof4(vv.x, vv.y);
        ((float4*)Vs)[idx * 2 + 1] = h4tof4(vv.z, vv.w);
    }
    __syncthreads();

    for (int q = w; q < T_; q += 8) {
        uint2 qraw = *(const uint2*)(base + (size_t)q * 3 * D_ + h * HD_ + lane * 4);
        float4 qv = h4tof4(qraw.x, qraw.y);
        for (int k = 0; k < T_; k++) {
            float4 kv = ((const float4*)Ks)[k * 32 + lane];
            float s = qv.x * kv.x + qv.y * kv.y + qv.z * kv.z + qv.w * kv.w;
#pragma unroll
            for (int off = 16; off; off >>= 1) s += __shfl_xor_sync(~0u, s, off);
            if (lane == 0) sbuf[w][k] = s * SCALE_;
        }
        __syncwarp();
        float m = -1e30f;
        for (int j = lane; j < T_; j += 32) m = fmaxf(m, sbuf[w][j]);
#pragma unroll
        for (int off = 16; off; off >>= 1) m = fmaxf(m, __shfl_xor_sync(~0u, m, off));
        float ssum = 0.f;
        for (int j = lane; j < T_; j += 32) {
            float e = expf(sbuf[w][j] - m);
            sbuf[w][j] = e;
            ssum += e;
        }
#pragma unroll
        for (int off = 16; off; off >>= 1) ssum += __shfl_xor_sync(~0u, ssum, off);
        float inv = 1.f / ssum;
        __syncwarp();
        float4 acc = make_float4(0.f, 0.f, 0.f, 0.f);
        for (int k = 0; k < T_; k++) {
            float a = sbuf[w][k];
            float4 vv = ((const float4*)Vs)[k * 32 + lane];
            acc.x += a * vv.x; acc.y += a * vv.y;
            acc.z += a * vv.z; acc.w += a * vv.w;
        }
        __half2* cp = (__half2*)(ctx + (size_t)(b * T_ + q) * D_ + h * HD_ + lane * 4);
        cp[0] = __floats2half2_rn(acc.x * inv, acc.y * inv);
        cp[1] = __floats2half2_rn(acc.z * inv, acc.w * inv);
        __syncwarp();
    }
}

// ---------------- LayerNorm (residual pre-added in GEMM epilogue) ---------
__global__ void ln_kernel(const float* __restrict__ tmp, float* __restrict__ h,
                          const float* __restrict__ g, const float* __restrict__ bta,
                          __half* __restrict__ h16) {
    int row = blockIdx.x;
    int tid = threadIdx.x, lane = tid & 31, w = tid >> 5;

    float4 v = ((const float4*)(tmp + (size_t)row * D_))[tid];

    float s = v.x + v.y + v.z + v.w;
    float sq = v.x * v.x + v.y * v.y + v.z * v.z + v.w * v.w;
#pragma unroll
    for (int off = 16; off; off >>= 1) {
        s += __shfl_xor_sync(~0u, s, off);
        sq += __shfl_xor_sync(~0u, sq, off);
    }
    __shared__ float ss[8], sqs[8];
    if (lane == 0) { ss[w] = s; sqs[w] = sq; }
    __syncthreads();
    float S = 0.f, SQ = 0.f;
#pragma unroll
    for (int i = 0; i < 8; i++) { S += ss[i]; SQ += sqs[i]; }
    float mean = S * (1.f / D_);
    float var = SQ * (1.f / D_) - mean * mean;
    float rstd = rsqrtf(var + 1e-5f);

    float4 gg = ((const float4*)g)[tid];
    float4 bb = ((const float4*)bta)[tid];
    float4 o;
    o.x = (v.x - mean) * rstd * gg.x + bb.x;
    o.y = (v.y - mean) * rstd * gg.y + bb.y;
    o.z = (v.z - mean) * rstd * gg.z + bb.z;
    o.w = (v.w - mean) * rstd * gg.w + bb.w;
    ((float4*)(h + (size_t)row * D_))[tid] = o;
    __half2* hp = (__half2*)(h16 + (size_t)row * D_) + tid * 2;
    hp[0] = __floats2half2_rn(o.x, o.y);
    hp[1] = __floats2half2_rn(o.z, o.w);
}

// ---------------- final split-K reduce (+bias) ----------------
__global__ void final_reduce(const float* __restrict__ part, const float* __restrict__ bo,
                             float* __restrict__ out) {
    int idx = blockIdx.x * 256 + threadIdx.x;
    float s = bo[idx & (OUT_ - 1)];
#pragma unroll 10
    for (int p = 0; p < SPLITF_; p++) s += part[(size_t)p * B_ * OUT_ + idx];
    out[idx] = s;
}

// ---------------- driver ----------------
extern "C" void kernel_launch(void* const* d_in, const int* in_sizes, int n_in,
                              void* d_out, int out_size) {
    const float* x     = (const float*)d_in[0];
    const float* Wi    = (const float*)d_in[1];
    const float* bi    = (const float*)d_in[2];
    const float* qkv_w = (const float*)d_in[3];
    const float* qkv_b = (const float*)d_in[4];
    const float* out_w = (const float*)d_in[5];
    const float* out_b = (const float*)d_in[6];
    const float* ff1_w = (const float*)d_in[7];
    const float* ff1_b = (const float*)d_in[8];
    const float* ff2_w = (const float*)d_in[9];
    const float* ff2_b = (const float*)d_in[10];
    const float* ln1_g = (const float*)d_in[11];
    const float* ln1_b = (const float*)d_in[12];
    const float* ln2_g = (const float*)d_in[13];
    const float* ln2_b = (const float*)d_in[14];
    const float* Wo    = (const float*)d_in[15];
    const float* bo    = (const float*)d_in[16];
    float* out = (float*)d_out;

    cudaFuncSetAttribute(attn_kernel, cudaFuncAttributeMaxDynamicSharedMemorySize,
                         2 * T_ * HD_ * (int)sizeof(float));
    cudaFuncSetAttribute(tc_gemm<false, true, true, false>,  cudaFuncAttributeMaxDynamicSharedMemorySize, GEMM_SMEM);
    cudaFuncSetAttribute(tc_gemm<false, true, false, true>,  cudaFuncAttributeMaxDynamicSharedMemorySize, GEMM_SMEM);
    cudaFuncSetAttribute(tc_gemm<true, true, true, false>,   cudaFuncAttributeMaxDynamicSharedMemorySize, GEMM_SMEM);
    cudaFuncSetAttribute(tc_gemm<false, false, false, false>,cudaFuncAttributeMaxDynamicSharedMemorySize, GEMM_SMEM);

    float *h_, *tmp_, *part_;
    __half *h16_, *qkv16_, *ctx16_, *ff16_;
    uint4 *qkvwp_, *outwp_, *ff1wp_, *ff2wp_, *wotp_;
    cudaGetSymbolAddress((void**)&h_,     g_h);
    cudaGetSymbolAddress((void**)&tmp_,   g_tmp);
    cudaGetSymbolAddress((void**)&part_,  g_part);
    cudaGetSymbolAddress((void**)&h16_,   g_h16);
    cudaGetSymbolAddress((void**)&qkv16_, g_qkv16);
    cudaGetSymbolAddress((void**)&ctx16_, g_ctx16);
    cudaGetSymbolAddress((void**)&ff16_,  g_ff16);
    cudaGetSymbolAddress((void**)&qkvwp_, g_qkvwp);
    cudaGetSymbolAddress((void**)&outwp_, g_outwp);
    cudaGetSymbolAddress((void**)&ff1wp_, g_ff1wp);
    cudaGetSymbolAddress((void**)&ff2wp_, g_ff2wp);
    cudaGetSymbolAddress((void**)&wotp_,  g_wotp);

    const size_t qkvw_s = (size_t)3 * D_ * D_, dw_s = (size_t)D_ * D_;
    const int qkv_blocks = (int)(qkvw_s / 8 / 256);   // 1536
    const int dw_blocks  = (int)(dw_s / 8 / 256);     // 512

    permw<<<dim3(qkv_blocks, L_), 256>>>(qkv_w, qkvwp_, 3 * D_, D_, qkvw_s, qkvw_s / 8); // idx 0
    embed_kernel<<<M_, 256>>>(x, Wi, bi, h_, h16_);                                      // idx 1

    for (int i = 0; i < L_; i++) {
        const uint4* qwp = qkvwp_ + (size_t)i * (qkvw_s / 8);
        const float* qb = qkv_b + (size_t)i * 3 * D_;
        const int NPQ = 3 * D_ / 16;  // 192
        if (i == 0) {
            tc_gemm<false, true, true, false><<<dim3(1536 / BN, M_ / BM, 1), 512, GEMM_SMEM>>>(
                h16_, qwp, qb, nullptr, qkv16_, M_, 3 * D_, D_, D_, NPQ, 0);          // idx 2
            tc_gemm<false, true, true, false><<<dim3(1536 / BN, M_ / BM, 1), 512, GEMM_SMEM>>>(
                h16_, qwp, qb + 1536, nullptr, qkv16_ + 1536, M_, 3 * D_, D_, D_, NPQ, 1536); // idx 3
        } else {
            tc_gemm<false, true, true, false><<<dim3(3 * D_ / BN, M_ / BM, 1), 512, GEMM_SMEM>>>(
                h16_, qwp, qb, nullptr, qkv16_, M_, 3 * D_, D_, D_, NPQ, 0);
        }
        attn_kernel<<<dim3(H_, B_), 256, 2 * T_ * HD_ * sizeof(float)>>>(qkv16_, ctx16_);
        if (i == 0) permw<<<dim3(dw_blocks, L_), 256>>>(out_w, outwp_, D_, D_, dw_s, dw_s / 8);
        tc_gemm<false, true, false, true><<<dim3(D_ / BN, M_ / BM, 1), 512, GEMM_SMEM>>>(
            ctx16_, outwp_ + (size_t)i * (dw_s / 8), out_b + (size_t)i * D_, h_,
            tmp_, M_, D_, D_, D_, D_ / 16, 0);
        ln_kernel<<<M_, 256>>>(tmp_, h_, ln1_g + (size_t)i * D_, ln1_b + (size_t)i * D_, h16_);
        if (i == 0) permw<<<dim3(dw_blocks, L_), 256>>>(ff1_w, ff1wp_, D_, D_, dw_s, dw_s / 8);
        tc_gemm<true, true, true, false><<<dim3(D_ / BN, M_ / BM, 1), 512, GEMM_SMEM>>>(
            h16_, ff1wp_ + (size_t)i * (dw_s / 8), ff1_b + (size_t)i * D_, nullptr,
            ff16_, M_, D_, D_, D_, D_ / 16, 0);
        if (i == 0) permw<<<dim3(dw_blocks, L_), 256>>>(ff2_w, ff2wp_, D_, D_, dw_s, dw_s / 8);
        tc_gemm<false, true, false, true><<<dim3(D_ / BN, M_ / BM, 1), 512, GEMM_SMEM>>>(
            ff16_, ff2wp_ + (size_t)i * (dw_s / 8), ff2_b + (size_t)i * D_, h_,
            tmp_, M_, D_, D_, D_, D_ / 16, 0);
        ln_kernel<<<M_, 256>>>(tmp_, h_, ln2_g + (size_t)i * D_, ln2_b + (size_t)i * D_, h16_);
        if (i == 0) permwo<<<(int)((size_t)OUT_ * KTOT_ / 8 / 256), 256>>>(Wo, wotp_);
    }

    tc_gemm<false, false, false, false><<<dim3(OUT_ / BN, B_ / BM, SPLITF_), 512, GEMM_SMEM>>>(
        h16_, wotp_, nullptr, nullptr, part_, B_, OUT_, KTOT_, KTOT_ / SPLITF_, OUT_ / 16, 0);
    final_reduce<<<(B_ * OUT_) / 256, 256>>>(part_, bo, out);
}

// round 15
// speedup vs baseline: 1.0292x; 1.0292x over previous
#include <cuda_runtime.h>
#include <cuda_fp16.h>
#include <math.h>
#include <stdint.h>

// ---------------- problem constants ----------------
#define B_   256
#define T_   100
#define IN_  6
#define D_   1024
#define H_   8
#define L_   4
#define OUT_ 256
#define HD_  128
#define M_   (B_ * T_)         // 25600
#define KTOT_ (T_ * D_)        // 102400
#define SPLITF_ 100            // kchunk = 1024
#define SCALE_ 0.08838834764831845f

// ---------------- GEMM tiling (r12 config: best) ----------------
#define BM 128
#define BN 128
#define BK 64
#define LDSH 72                             // A row pitch 144B, conflict-free
#define STAGE_H (BM * LDSH)                 // 9216 halves = 18432 B
#define STAGES 3
#define GEMM_SMEM (STAGES * STAGE_H * 2)    // 55296 B -> 2 CTAs/SM

// ---------------- scratch (device globals) ----------------
__device__ float  g_h[M_ * D_];
__device__ float  g_part[SPLITF_ * B_ * OUT_];
__device__ __half g_tmp16[M_ * D_];         // pre-LN sum, fp16
__device__ __half g_h16[M_ * D_];
__device__ __half g_qkv16[M_ * 3 * D_];
__device__ __half g_ctx16[M_ * D_];
__device__ __half g_ff16[M_ * D_];
// fragment-pair-permuted weights: uint4 per (pair, lane); pair idx = kf*NP + np
__device__ uint4  g_qkvwp[L_ * 3 * D_ * D_ / 8];
__device__ uint4  g_outwp[L_ * D_ * D_ / 8];
__device__ uint4  g_ff1wp[L_ * D_ * D_ / 8];
__device__ uint4  g_ff2wp[L_ * D_ * D_ / 8];
__device__ uint4  g_wotp[(size_t)OUT_ * KTOT_ / 8];

// ---------------- helpers ----------------
__device__ __forceinline__ uint32_t smem_u32(const void* p) {
    uint32_t a;
    asm("{ .reg .u64 t; cvta.to.shared.u64 t, %1; cvt.u32.u64 %0, t; }" : "=r"(a) : "l"(p));
    return a;
}
#define CP_ASYNC16(dst, src) asm volatile("cp.async.cg.shared.global [%0], [%1], 16;" :: "r"(dst), "l"(src) : "memory")
#define CP_COMMIT()          asm volatile("cp.async.commit_group;" ::: "memory")
#define CP_WAIT1()           asm volatile("cp.async.wait_group 1;" ::: "memory")

__device__ __forceinline__ void ldsm_x4(uint32_t* r, uint32_t addr) {
    asm volatile("ldmatrix.sync.aligned.m8n8.x4.shared.b16 {%0,%1,%2,%3}, [%4];"
                 : "=r"(r[0]), "=r"(r[1]), "=r"(r[2]), "=r"(r[3]) : "r"(addr));
}

__device__ __forceinline__ void mma_f16(float* d, const uint32_t* a, uint32_t b0, uint32_t b1) {
    asm volatile(
        "mma.sync.aligned.m16n8k16.row.col.f32.f16.f16.f32 "
        "{%0,%1,%2,%3}, {%4,%5,%6,%7}, {%8,%9}, {%0,%1,%2,%3};"
        : "+f"(d[0]), "+f"(d[1]), "+f"(d[2]), "+f"(d[3])
        : "r"(a[0]), "r"(a[1]), "r"(a[2]), "r"(a[3]), "r"(b0), "r"(b1));
}

__device__ __forceinline__ float4 h4tof4(uint32_t u0, uint32_t u1) {
    float2 f0 = __half22float2(*(__half2*)&u0);
    float2 f1 = __half22float2(*(__half2*)&u1);
    return make_float4(f0.x, f0.y, f1.x, f1.y);
}

// ===== fp16 GEMM (r12): A smem+ldmatrix, B LDG.128 pair-permuted ====
// C[M,N] = A[M,lda] @ W^T (+bias)(+res)(+relu). grid (N/BN, M/BM, splits).
// HOUT: C is __half (row-major). ADDRES (requires HOUT here): adds fp32 res.
template <bool RELU, bool HASBIAS, bool HOUT, bool ADDRES>
__global__ void __launch_bounds__(256, 2)
tc_gemm(const __half* __restrict__ A, const uint4* __restrict__ Wp,
        const float* __restrict__ bias, const float* __restrict__ res,
        void* __restrict__ Cv, int M, int N, int lda, int kchunk,
        int NP, int ncoff) {
    extern __shared__ __half smh[];
    uint32_t sbase = smem_u32(smh);

    int tid = threadIdx.x;
    int lane = tid & 31, wid = tid >> 5;
    int wm = wid & 3, wn = wid >> 2;                 // 4x2 grid, 32x64 per warp
    int m0 = blockIdx.y * BM, n0 = blockIdx.x * BN;
    int kbeg = blockIdx.z * kchunk;
    int kf0 = kbeg >> 4;
    int npw = (ncoff + n0 + wn * 64) >> 4;           // first of 4 B frag-pairs

    const __half* asrc[4];
    uint32_t adst[4];
#pragma unroll
    for (int j = 0; j < 4; j++) {
        int c = tid + 256 * j;
        int r = c >> 3, c8 = c & 7;
        asrc[j] = A + (size_t)(m0 + r) * lda + kbeg + c8 * 8;
        adst[j] = (uint32_t)(r * LDSH + c8 * 8) * 2;
    }

    float acc[2][8][4];
#pragma unroll
    for (int tm = 0; tm < 2; tm++)
#pragma unroll
        for (int tn = 0; tn < 8; tn++)
#pragma unroll
            for (int c = 0; c < 4; c++) acc[tm][tn][c] = 0.f;

    const int NITER = kchunk / BK;

#pragma unroll
    for (int s = 0; s < 2; s++) {
        uint32_t sb = sbase + (uint32_t)(s * STAGE_H * 2);
        int ko = s * BK;
#pragma unroll
        for (int j = 0; j < 4; j++) CP_ASYNC16(sb + adst[j], asrc[j] + ko);
        CP_COMMIT();
    }

    int lrow = lane & 15;
    int lkb  = (lane >> 4) * 16;
    int buf = 0;

    for (int it = 0; it < NITER; it++) {
        CP_WAIT1();
        __syncthreads();

        if (it + 2 < NITER) {
            int s = it + 2;
            int sb3 = s;  while (sb3 >= STAGES) sb3 -= STAGES;
            uint32_t sbs = sbase + (uint32_t)(sb3 * STAGE_H * 2);
            int ko = s * BK;
#pragma unroll
            for (int j = 0; j < 4; j++) CP_ASYNC16(sbs + adst[j], asrc[j] + ko);
        }
        CP_COMMIT();

        uint32_t sa = sbase + (uint32_t)(buf * STAGE_H * 2)
                    + (uint32_t)((wm * 32 + lrow) * (LDSH * 2)) + lkb;

#pragma unroll
        for (int ks = 0; ks < 4; ks++) {
            int kf = kf0 + it * 4 + ks;
            const uint4* bp = Wp + ((size_t)kf * NP + npw) * 32 + lane;
            uint4 bf[4];
#pragma unroll
            for (int f = 0; f < 4; f++) bf[f] = __ldg(bp + f * 32);

            int kbyte = ks * 32;
            uint32_t afr[2][4];
            ldsm_x4(afr[0], sa + kbyte);
            ldsm_x4(afr[1], sa + 16 * (LDSH * 2) + kbyte);
#pragma unroll
            for (int tnp = 0; tnp < 4; tnp++) {
                mma_f16(acc[0][tnp * 2],     afr[0], bf[tnp].x, bf[tnp].y);
                mma_f16(acc[0][tnp * 2 + 1], afr[0], bf[tnp].z, bf[tnp].w);
                mma_f16(acc[1][tnp * 2],     afr[1], bf[tnp].x, bf[tnp].y);
                mma_f16(acc[1][tnp * 2 + 1], afr[1], bf[tnp].z, bf[tnp].w);
            }
        }

        buf = (buf + 1 == STAGES) ? 0 : buf + 1;
    }

    // ---- epilogue: bias + residual + relu ----
    int q = lane & 3, g = lane >> 2;
#pragma unroll
    for (int tm = 0; tm < 2; tm++) {
        int row = m0 + wm * 32 + tm * 16 + g;
#pragma unroll
        for (int tn = 0; tn < 8; tn++) {
            int col = n0 + wn * 64 + tn * 8 + 2 * q;
            float b0 = 0.f, b1 = 0.f;
            if (HASBIAS) { b0 = bias[col]; b1 = bias[col + 1]; }
            float v00 = acc[tm][tn][0] + b0, v01 = acc[tm][tn][1] + b1;
            float v10 = acc[tm][tn][2] + b0, v11 = acc[tm][tn][3] + b1;
            if (ADDRES) {
                float2 r0 = *(const float2*)(res + (size_t)row * N + col);
                float2 r1 = *(const float2*)(res + (size_t)(row + 8) * N + col);
                v00 += r0.x; v01 += r0.y; v10 += r1.x; v11 += r1.y;
            }
            if (RELU) {
                v00 = fmaxf(v00, 0.f); v01 = fmaxf(v01, 0.f);
                v10 = fmaxf(v10, 0.f); v11 = fmaxf(v11, 0.f);
            }
            if (HOUT) {
                __half* C = (__half*)Cv + (size_t)blockIdx.z * M * N;
                *(__half2*)(C + (size_t)row * N + col) = __floats2half2_rn(v00, v01);
                *(__half2*)(C + (size_t)(row + 8) * N + col) = __floats2half2_rn(v10, v11);
            } else {
                float* C = (float*)Cv + (size_t)blockIdx.z * M * N;
                *(float2*)(C + (size_t)row * N + col) = make_float2(v00, v01);
                *(float2*)(C + (size_t)(row + 8) * N + col) = make_float2(v10, v11);
            }
        }
    }
}

// ---- weight prep: W[N,K] fp32 -> fragment-PAIR-permuted fp16 uint4 ----
__global__ void permw(const float* __restrict__ W, uint4* __restrict__ Wp,
                      int N, int K, size_t wstride, size_t pstride) {
    const float* Wl = W + wstride * blockIdx.y;
    uint4* Wpl = Wp + pstride * blockIdx.y;
    size_t idx = (size_t)blockIdx.x * 256 + threadIdx.x;
    int lane = (int)(idx & 31);
    size_t pr = idx >> 5;
    int NP = N >> 4;
    int np = (int)(pr % NP), kf = (int)(pr / NP);
    int ne = np * 16 + (lane >> 2);
    int k = kf * 16 + 2 * (lane & 3);
    const float* pe = Wl + (size_t)ne * K + k;
    const float* po = pe + (size_t)8 * K;
    __half2 xe = __floats2half2_rn(pe[0], pe[1]);
    __half2 ye = __floats2half2_rn(pe[8], pe[9]);
    __half2 xo = __floats2half2_rn(po[0], po[1]);
    __half2 yo = __floats2half2_rn(po[8], po[9]);
    Wpl[idx] = make_uint4(*(uint32_t*)&xe, *(uint32_t*)&ye,
                          *(uint32_t*)&xo, *(uint32_t*)&yo);
}

__global__ void permwo(const float* __restrict__ Wo, uint4* __restrict__ Wp) {
    size_t idx = (size_t)blockIdx.x * 256 + threadIdx.x;
    int lane = (int)(idx & 31);
    size_t pr = idx >> 5;
    const int NP = OUT_ >> 4;
    int np = (int)(pr % NP), kf = (int)(pr / NP);
    int ne = np * 16 + (lane >> 2);
    int k = kf * 16 + 2 * (lane & 3);
    const float* pe = Wo + (size_t)k * OUT_ + ne;
    __half2 xe = __floats2half2_rn(pe[0], pe[OUT_]);
    __half2 ye = __floats2half2_rn(pe[(size_t)8 * OUT_], pe[(size_t)9 * OUT_]);
    __half2 xo = __floats2half2_rn(pe[8], pe[OUT_ + 8]);
    __half2 yo = __floats2half2_rn(pe[(size_t)8 * OUT_ + 8], pe[(size_t)9 * OUT_ + 8]);
    Wp[idx] = make_uint4(*(uint32_t*)&xe, *(uint32_t*)&ye,
                         *(uint32_t*)&xo, *(uint32_t*)&yo);
}

// ---------------- embed ----------------
__global__ void embed_kernel(const float* __restrict__ x, const float* __restrict__ Wi,
                             const float* __restrict__ bi,
                             float* __restrict__ h, __half* __restrict__ h16) {
    int row = blockIdx.x;
    int t = row % T_;
    int d0 = threadIdx.x * 4;
    float xr[IN_];
#pragma unroll
    for (int j = 0; j < IN_; j++) xr[j] = x[row * IN_ + j];
    float4 o; float* op = &o.x;
#pragma unroll
    for (int c = 0; c < 4; c++) {
        int d = d0 + c;
        float acc = bi[d];
#pragma unroll
        for (int j = 0; j < IN_; j++) acc += xr[j] * Wi[j * D_ + d];
        int i2 = (d >> 1) * 2;
        float div = expf((float)i2 * (-9.210340371976184f / (float)D_));
        float ang = (float)t * div;
        acc += (d & 1) ? cosf(ang) : sinf(ang);
        op[c] = acc;
    }
    *(float4*)(h + (size_t)row * D_ + d0) = o;
    __half2* hp = (__half2*)(h16 + (size_t)row * D_ + d0);
    hp[0] = __floats2half2_rn(o.x, o.y);
    hp[1] = __floats2half2_rn(o.z, o.w);
}

// ---------------- fused attention per (b, h) ----------------
__global__ void attn_kernel(const __half* __restrict__ qkv, __half* __restrict__ ctx) {
    extern __shared__ float smf[];
    float* Ks = smf;
    float* Vs = smf + T_ * HD_;
    __shared__ float sbuf[8][104];

    int h = blockIdx.x, b = blockIdx.y;
    int tid = threadIdx.x, lane = tid & 31, w = tid >> 5;
    const __half* base = qkv + (size_t)b * T_ * 3 * D_;

    for (int idx = tid; idx < T_ * (HD_ / 8); idx += 256) {
        int k = idx >> 4, dq = idx & 15;
        const __half* rp = base + (size_t)k * 3 * D_ + h * HD_ + dq * 8;
        uint4 kv = *(const uint4*)(rp + D_);
        uint4 vv = *(const uint4*)(rp + 2 * D_);
        ((float4*)Ks)[idx * 2]     = h4tof4(kv.x, kv.y);
        ((float4*)Ks)[idx * 2 + 1] = h4tof4(kv.z, kv.w);
        ((float4*)Vs)[idx * 2]     = h4tof4(vv.x, vv.y);
        ((float4*)Vs)[idx * 2 + 1] = h4tof4(vv.z, vv.w);
    }
    __syncthreads();

    for (int q = w; q < T_; q += 8) {
        uint2 qraw = *(const uint2*)(base + (size_t)q * 3 * D_ + h * HD_ + lane * 4);
        float4 qv = h4tof4(qraw.x, qraw.y);
        for (int k = 0; k < T_; k++) {
            float4 kv = ((const float4*)Ks)[k * 32 + lane];
            float s = qv.x * kv.x + qv.y * kv.y + qv.z * kv.z + qv.w * kv.w;
#pragma unroll
            for (int off = 16; off; off >>= 1) s += __shfl_xor_sync(~0u, s, off);
            if (lane == 0) sbuf[w][k] = s * SCALE_;
        }
        __syncwarp();
        float m = -1e30f;
        for (int j = lane; j < T_; j += 32) m = fmaxf(m, sbuf[w][j]);
#pragma unroll
        for (int off = 16; off; off >>= 1) m = fmaxf(m, __shfl_xor_sync(~0u, m, off));
        float ssum = 0.f;
        for (int j = lane; j < T_; j += 32) {
            float e = expf(sbuf[w][j] - m);
            sbuf[w][j] = e;
            ssum += e;
        }
#pragma unroll
        for (int off = 16; off; off >>= 1) ssum += __shfl_xor_sync(~0u, ssum, off);
        float inv = 1.f / ssum;
        __syncwarp();
        float4 acc = make_float4(0.f, 0.f, 0.f, 0.f);
        for (int k = 0; k < T_; k++) {
            float a = sbuf[w][k];
            float4 vv = ((const float4*)Vs)[k * 32 + lane];
            acc.x += a * vv.x; acc.y += a * vv.y;
            acc.z += a * vv.z; acc.w += a * vv.w;
        }
        __half2* cp = (__half2*)(ctx + (size_t)(b * T_ + q) * D_ + h * HD_ + lane * 4);
        cp[0] = __floats2half2_rn(acc.x * inv, acc.y * inv);
        cp[1] = __floats2half2_rn(acc.z * inv, acc.w * inv);
        __syncwarp();
    }
}

// ---------------- LayerNorm: tmp16 (fp16 sum) -> h fp32 + h16 ------------
// 512 threads, 2 rows per block; per-row math identical to the 256-thread version.
__global__ void ln_kernel(const __half* __restrict__ tmp16, float* __restrict__ h,
                          const float* __restrict__ g, const float* __restrict__ bta,
                          __half* __restrict__ h16) {
    int half_ = threadIdx.x >> 8;              // 0 or 1 -> row within block
    int row = blockIdx.x * 2 + half_;
    int rtid = threadIdx.x & 255;
    int lane = rtid & 31, w = rtid >> 5;

    uint2 raw = ((const uint2*)(tmp16 + (size_t)row * D_))[rtid];
    float4 v = h4tof4(raw.x, raw.y);

    float s = v.x + v.y + v.z + v.w;
    float sq = v.x * v.x + v.y * v.y + v.z * v.z + v.w * v.w;
#pragma unroll
    for (int off = 16; off; off >>= 1) {
        s += __shfl_xor_sync(~0u, s, off);
        sq += __shfl_xor_sync(~0u, sq, off);
    }
    __shared__ float ss[2][8], sqs[2][8];
    if (lane == 0) { ss[half_][w] = s; sqs[half_][w] = sq; }
    __syncthreads();
    float S = 0.f, SQ = 0.f;
#pragma unroll
    for (int i = 0; i < 8; i++) { S += ss[half_][i]; SQ += sqs[half_][i]; }
    float mean = S * (1.f / D_);
    float var = SQ * (1.f / D_) - mean * mean;
    float rstd = rsqrtf(var + 1e-5f);

    float4 gg = ((const float4*)g)[rtid];
    float4 bb = ((const float4*)bta)[rtid];
    float4 o;
    o.x = (v.x - mean) * rstd * gg.x + bb.x;
    o.y = (v.y - mean) * rstd * gg.y + bb.y;
    o.z = (v.z - mean) * rstd * gg.z + bb.z;
    o.w = (v.w - mean) * rstd * gg.w + bb.w;
    ((float4*)(h + (size_t)row * D_))[rtid] = o;
    __half2* hp = (__half2*)(h16 + (size_t)row * D_) + rtid * 2;
    hp[0] = __floats2half2_rn(o.x, o.y);
    hp[1] = __floats2half2_rn(o.z, o.w);
}

// ---------------- final split-K reduce (+bias) ----------------
__global__ void final_reduce(const float* __restrict__ part, const float* __restrict__ bo,
                             float* __restrict__ out) {
    int idx = blockIdx.x * 256 + threadIdx.x;
    float s = bo[idx & (OUT_ - 1)];
#pragma unroll 10
    for (int p = 0; p < SPLITF_; p++) s += part[(size_t)p * B_ * OUT_ + idx];
    out[idx] = s;
}

// ---------------- driver ----------------
extern "C" void kernel_launch(void* const* d_in, const int* in_sizes, int n_in,
                              void* d_out, int out_size) {
    const float* x     = (const float*)d_in[0];
    const float* Wi    = (const float*)d_in[1];
    const float* bi    = (const float*)d_in[2];
    const float* qkv_w = (const float*)d_in[3];
    const float* qkv_b = (const float*)d_in[4];
    const float* out_w = (const float*)d_in[5];
    const float* out_b = (const float*)d_in[6];
    const float* ff1_w = (const float*)d_in[7];
    const float* ff1_b = (const float*)d_in[8];
    const float* ff2_w = (const float*)d_in[9];
    const float* ff2_b = (const float*)d_in[10];
    const float* ln1_g = (const float*)d_in[11];
    const float* ln1_b = (const float*)d_in[12];
    const float* ln2_g = (const float*)d_in[13];
    const float* ln2_b = (const float*)d_in[14];
    const float* Wo    = (const float*)d_in[15];
    const float* bo    = (const float*)d_in[16];
    float* out = (float*)d_out;

    cudaFuncSetAttribute(attn_kernel, cudaFuncAttributeMaxDynamicSharedMemorySize,
                         2 * T_ * HD_ * (int)sizeof(float));
    cudaFuncSetAttribute(tc_gemm<false, true, true, false>,  cudaFuncAttributeMaxDynamicSharedMemorySize, GEMM_SMEM);
    cudaFuncSetAttribute(tc_gemm<false, true, true, true>,   cudaFuncAttributeMaxDynamicSharedMemorySize, GEMM_SMEM);
    cudaFuncSetAttribute(tc_gemm<true, true, true, false>,   cudaFuncAttributeMaxDynamicSharedMemorySize, GEMM_SMEM);
    cudaFuncSetAttribute(tc_gemm<false, false, false, false>,cudaFuncAttributeMaxDynamicSharedMemorySize, GEMM_SMEM);

    float *h_, *part_;
    __half *tmp16_, *h16_, *qkv16_, *ctx16_, *ff16_;
    uint4 *qkvwp_, *outwp_, *ff1wp_, *ff2wp_, *wotp_;
    cudaGetSymbolAddress((void**)&h_,     g_h);
    cudaGetSymbolAddress((void**)&part_,  g_part);
    cudaGetSymbolAddress((void**)&tmp16_, g_tmp16);
    cudaGetSymbolAddress((void**)&h16_,   g_h16);
    cudaGetSymbolAddress((void**)&qkv16_, g_qkv16);
    cudaGetSymbolAddress((void**)&ctx16_, g_ctx16);
    cudaGetSymbolAddress((void**)&ff16_,  g_ff16);
    cudaGetSymbolAddress((void**)&qkvwp_, g_qkvwp);
    cudaGetSymbolAddress((void**)&outwp_, g_outwp);
    cudaGetSymbolAddress((void**)&ff1wp_, g_ff1wp);
    cudaGetSymbolAddress((void**)&ff2wp_, g_ff2wp);
    cudaGetSymbolAddress((void**)&wotp_,  g_wotp);

    const size_t qkvw_s = (size_t)3 * D_ * D_, dw_s = (size_t)D_ * D_;
    const int qkv_blocks = (int)(qkvw_s / 8 / 256);   // 1536
    const int dw_blocks  = (int)(dw_s / 8 / 256);     // 512

    permw<<<dim3(qkv_blocks, L_), 256>>>(qkv_w, qkvwp_, 3 * D_, D_, qkvw_s, qkvw_s / 8); // idx 0
    embed_kernel<<<M_, 256>>>(x, Wi, bi, h_, h16_);                                      // idx 1

    for (int i = 0; i < L_; i++) {
        const uint4* qwp = qkvwp_ + (size_t)i * (qkvw_s / 8);
        const float* qb = qkv_b + (size_t)i * 3 * D_;
        const int NPQ = 3 * D_ / 16;  // 192
        if (i == 0) {
            tc_gemm<false, true, true, false><<<dim3(1536 / BN, M_ / BM, 1), 256, GEMM_SMEM>>>(
                h16_, qwp, qb, nullptr, qkv16_, M_, 3 * D_, D_, D_, NPQ, 0);          // idx 2
            tc_gemm<false, true, true, false><<<dim3(1536 / BN, M_ / BM, 1), 256, GEMM_SMEM>>>(
                h16_, qwp, qb + 1536, nullptr, qkv16_ + 1536, M_, 3 * D_, D_, D_, NPQ, 1536); // idx 3
        } else {
            tc_gemm<false, true, true, false><<<dim3(3 * D_ / BN, M_ / BM, 1), 256, GEMM_SMEM>>>(
                h16_, qwp, qb, nullptr, qkv16_, M_, 3 * D_, D_, D_, NPQ, 0);
        }
        attn_kernel<<<dim3(H_, B_), 256, 2 * T_ * HD_ * sizeof(float)>>>(qkv16_, ctx16_);
        if (i == 0) permw<<<dim3(dw_blocks, L_), 256>>>(out_w, outwp_, D_, D_, dw_s, dw_s / 8);
        // out-proj: tmp16 = half(h + ctx @ outw^T + b)
        tc_gemm<false, true, true, true><<<dim3(D_ / BN, M_ / BM, 1), 256, GEMM_SMEM>>>(
            ctx16_, outwp_ + (size_t)i * (dw_s / 8), out_b + (size_t)i * D_, h_,
            tmp16_, M_, D_, D_, D_, D_ / 16, 0);
        ln_kernel<<<M_ / 2, 512>>>(tmp16_, h_, ln1_g + (size_t)i * D_, ln1_b + (size_t)i * D_, h16_);
        if (i == 0) permw<<<dim3(dw_blocks, L_), 256>>>(ff1_w, ff1wp_, D_, D_, dw_s, dw_s / 8);
        tc_gemm<true, true, true, false><<<dim3(D_ / BN, M_ / BM, 1), 256, GEMM_SMEM>>>(
            h16_, ff1wp_ + (size_t)i * (dw_s / 8), ff1_b + (size_t)i * D_, nullptr,
            ff16_, M_, D_, D_, D_, D_ / 16, 0);
        if (i == 0) permw<<<dim3(dw_blocks, L_), 256>>>(ff2_w, ff2wp_, D_, D_, dw_s, dw_s / 8);
        // ff2: tmp16 = half(h + ff @ ff2w^T + b)
        tc_gemm<false, true, true, true><<<dim3(D_ / BN, M_ / BM, 1), 256, GEMM_SMEM>>>(
            ff16_, ff2wp_ + (size_t)i * (dw_s / 8), ff2_b + (size_t)i * D_, h_,
            tmp16_, M_, D_, D_, D_, D_ / 16, 0);
        ln_kernel<<<M_ / 2, 512>>>(tmp16_, h_, ln2_g + (size_t)i * D_, ln2_b + (size_t)i * D_, h16_);
        if (i == 0) permwo<<<(int)((size_t)OUT_ * KTOT_ / 8 / 256), 256>>>(Wo, wotp_);
    }

    tc_gemm<false, false, false, false><<<dim3(OUT_ / BN, B_ / BM, SPLITF_), 256, GEMM_SMEM>>>(
        h16_, wotp_, nullptr, nullptr, part_, B_, OUT_, KTOT_, KTOT_ / SPLITF_, OUT_ / 16, 0);
    final_reduce<<<(B_ * OUT_) / 256, 256>>>(part_, bo, out);
}